// round 9
// baseline (speedup 1.0000x reference)
#include <cuda_runtime.h>
#include <cuda_fp16.h>
#include <cstdint>
#include <cstddef>
#include <math.h>

#define NE    8
#define DD    1024
#define FF    4096
#define CAPN  4096
#define NT    16384     // B*T tokens

// ----------------------------- static scratch ------------------------------
__device__ unsigned g_keys[NE * NT];
__device__ int      g_sel [NE * CAPN];             // slot -> token
__device__ int      g_inv [NE * NT];               // (e,token) -> slot or -1
__device__ __half   g_W1t[(size_t)NE * FF * DD];   // [e][f][d] K-major
__device__ __half   g_W2t[(size_t)NE * DD * FF];   // [e][d][f] K-major
__device__ __half   g_Xp [(size_t)NE * CAPN * DD]; // gathered tokens fp16
__device__ __half   g_H  [(size_t)NE * CAPN * FF]; // gelu(X@W1+b1) fp16
__device__ __half   g_Yh [(size_t)NE * CAPN * DD]; // H@W2+b2 fp16

// ----------------------------- helpers -------------------------------------
#define DEV __device__ __forceinline__

DEV uint32_t smem_u32(const void* p) {
    uint32_t a;
    asm("{ .reg .u64 t; cvta.to.shared.u64 t, %1; cvt.u32.u64 %0, t; }"
        : "=r"(a) : "l"(p));
    return a;
}

DEV uint32_t sw128(uint32_t off) { return off ^ ((off >> 3) & 0x70); }

DEV void cp16(uint32_t saddr, const void* g) {
    asm volatile("cp.async.cg.shared.global [%0], [%1], 16;" :: "r"(saddr), "l"(g));
}
#define CP_COMMIT() asm volatile("cp.async.commit_group;" ::: "memory")
#define CP_WAIT1()  asm volatile("cp.async.wait_group 1;" ::: "memory")

DEV void ldsm4(uint32_t* r, uint32_t addr) {
    asm volatile("ldmatrix.sync.aligned.m8n8.x4.shared.b16 {%0,%1,%2,%3}, [%4];"
        : "=r"(r[0]), "=r"(r[1]), "=r"(r[2]), "=r"(r[3]) : "r"(addr));
}

DEV void mma16816(float* c, const uint32_t* a, const uint32_t* b) {
    asm volatile("mma.sync.aligned.m16n8k16.row.col.f32.f16.f16.f32 "
        "{%0,%1,%2,%3}, {%4,%5,%6,%7}, {%8,%9}, {%0,%1,%2,%3};"
        : "+f"(c[0]), "+f"(c[1]), "+f"(c[2]), "+f"(c[3])
        : "r"(a[0]), "r"(a[1]), "r"(a[2]), "r"(a[3]), "r"(b[0]), "r"(b[1]));
}

// ----------------------------- GEMM ----------------------------------------
// Persistent-CTA HMMA GEMM. CTA tile 128x128, BK=64, 3-stage cp.async,
// 256 thr (8 warps, warp tile 64x32), 2 CTAs/SM. Each CTA chains many tiles;
// cp.async prefetch crosses tile boundaries so the pipeline never drains, and
// the (smem-free) epilogue overlaps the next tile's loads.
#define BM 128
#define BN 128
#define BK 64
#define STAGES 3
#define A_BYTES (BM * BK * 2)               // 16384
#define STAGE_BYTES (2 * A_BYTES)           // 32768 (A + B)
#define SMEM_TOTAL (STAGES * STAGE_BYTES)   // 98304

// GELU=true : C=gelu(Xp@W1t^T + b1) -> g_H (fp16), K=1024, N total=4096
// GELU=false: C=H @W2t^T + b2       -> g_Yh (fp16), K=4096, N total=1024
template<bool GELU>
__global__ void __launch_bounds__(256, 2) gemm_kernel(const float* __restrict__ bias) {
    constexpr int K    = GELU ? DD : FF;
    constexpr int NTOT = GELU ? FF : DD;
    constexpr int KT   = K / BK;
    constexpr int NTN  = NTOT / BN;              // 32 (gemm1) / 8 (gemm2)
    constexpr int TT   = NE * (CAPN / BM) * NTN; // total tiles

    extern __shared__ char smem[];
    const uint32_t sb = smem_u32(smem);
    const int tid = threadIdx.x;
    const int lane = tid & 31, wid = tid >> 5;
    const int wm = wid >> 2, wn = wid & 3;       // warp: 64x32 of 128x128

    const int P = gridDim.x;
    const int t0 = (int)(((long long)TT * blockIdx.x) / P);
    const int t1 = (int)(((long long)TT * (blockIdx.x + 1)) / P);
    if (t0 >= t1) return;

    const __half* Abase = GELU ? g_Xp  : g_H;
    const __half* Wbase = GELU ? g_W1t : g_W2t;

    auto tileA = [&](int t) -> const __half* {
        int r = t / NTN;                          // e*32 + mt
        return Abase + ((size_t)(r >> 5) * CAPN + (size_t)(r & 31) * BM) * K;
    };
    auto tileB = [&](int t) -> const __half* {
        int nt = t % NTN; int e = (t / NTN) >> 5;
        return Wbase + ((size_t)e * NTOT + (size_t)nt * BN) * K;
    };

    // per-stage loads: 1024 A-chunks + 1024 B-chunks of 16B; 8 per thread
    auto load_stage = [&](const __half* A, const __half* B, int c, int s) {
        const uint32_t sAb = sb + s * STAGE_BYTES;
        const uint32_t sBb = sAb + A_BYTES;
        const __half* As = A + c * BK;
        const __half* Bs = B + c * BK;
        #pragma unroll
        for (int i = 0; i < 4; ++i) {
            int u = tid + i * 256;                // < 1024
            int row = u >> 3, ch = u & 7;
            cp16(sAb + sw128(row * 128 + ch * 16), As + (size_t)row * K + ch * 8);
        }
        #pragma unroll
        for (int i = 0; i < 4; ++i) {
            int u = tid + i * 256;
            int row = u >> 3, ch = u & 7;
            cp16(sBb + sw128(row * 128 + ch * 16), Bs + (size_t)row * K + ch * 8);
        }
        CP_COMMIT();
    };

    // ldmatrix per-lane address components
    const int sel = lane >> 3;
    const int aRow = wm * 64 + (lane & 7) + ((sel & 1) << 3);   // + mi*16
    const int aCh  = sel >> 1;                                   // + 2*kk
    const int bRow = wn * 32 + (lane & 7) + ((sel >> 1) << 3);   // + np*16
    const int bCh  = sel & 1;                                    // + 2*kk

    float acc[4][4][4];
    #pragma unroll
    for (int mi = 0; mi < 4; ++mi)
        #pragma unroll
        for (int ni = 0; ni < 4; ++ni)
            #pragma unroll
            for (int q = 0; q < 4; ++q) acc[mi][ni][q] = 0.f;

    const __half* Ag = tileA(t0);
    const __half* Bg = tileB(t0);
    load_stage(Ag, Bg, 0, 0);
    load_stage(Ag, Bg, 1, 1);
    int s = 0;                                    // compute stage of next chunk

    for (int t = t0; t < t1; ++t) {
        const bool  has_next = (t + 1 < t1);
        const __half* An = has_next ? tileA(t + 1) : (const __half*)0;
        const __half* Bn = has_next ? tileB(t + 1) : (const __half*)0;

        for (int c = 0; c < KT; ++c) {
            CP_WAIT1();
            __syncthreads();

            int sp = s + 2; if (sp >= STAGES) sp -= STAGES;
            if (c + 2 < KT)      load_stage(Ag, Bg, c + 2, sp);
            else if (has_next)   load_stage(An, Bn, c + 2 - KT, sp);
            else                 CP_COMMIT();

            const uint32_t sA = sb + s * STAGE_BYTES;
            const uint32_t sB = sA + A_BYTES;

            #pragma unroll
            for (int kk = 0; kk < 4; ++kk) {
                uint32_t a[4][4];
                #pragma unroll
                for (int mi = 0; mi < 4; ++mi)
                    ldsm4(a[mi], sA + sw128((aRow + mi * 16) * 128 + (2 * kk + aCh) * 16));
                uint32_t b[4][2];
                #pragma unroll
                for (int np = 0; np < 2; ++np) {
                    uint32_t r[4];
                    ldsm4(r, sB + sw128((bRow + np * 16) * 128 + (2 * kk + bCh) * 16));
                    b[2 * np][0] = r[0]; b[2 * np][1] = r[1];
                    b[2 * np + 1][0] = r[2]; b[2 * np + 1][1] = r[3];
                }
                #pragma unroll
                for (int mi = 0; mi < 4; ++mi)
                    #pragma unroll
                    for (int ni = 0; ni < 4; ++ni)
                        mma16816(acc[mi][ni], a[mi], b[ni]);
            }
            if (++s == STAGES) s = 0;
        }

        // ---------------- epilogue for tile t (no smem, overlaps prefetch) --
        {
            const int nt = t % NTN; const int r = t / NTN;
            const int mt = r & 31;  const int e = r >> 5;
            const float* brow = bias + (size_t)e * NTOT + (size_t)nt * BN;
            const int g = lane >> 2, i2 = (lane & 3) * 2;
            #pragma unroll
            for (int mi = 0; mi < 4; ++mi) {
                #pragma unroll
                for (int h = 0; h < 2; ++h) {
                    const size_t crow = (size_t)e * CAPN + (size_t)mt * BM
                                      + wm * 64 + mi * 16 + g + 8 * h;
                    #pragma unroll
                    for (int ni = 0; ni < 4; ++ni) {
                        const int lcol = wn * 32 + ni * 8 + i2;
                        float v0 = acc[mi][ni][2 * h + 0] + brow[lcol + 0];
                        float v1 = acc[mi][ni][2 * h + 1] + brow[lcol + 1];
                        if (GELU) {
                            v0 = 0.5f * v0 * (1.0f + erff(v0 * 0.70710678118654752f));
                            v1 = 0.5f * v1 * (1.0f + erff(v1 * 0.70710678118654752f));
                            __half2 h2 = __floats2half2_rn(v0, v1);
                            *(__half2*)(g_H + crow * FF + nt * BN + lcol) = h2;
                        } else {
                            __half2 h2 = __floats2half2_rn(v0, v1);
                            *(__half2*)(g_Yh + crow * DD + nt * BN + lcol) = h2;
                        }
                    }
                }
            }
        }
        #pragma unroll
        for (int mi = 0; mi < 4; ++mi)
            #pragma unroll
            for (int ni = 0; ni < 4; ++ni)
                #pragma unroll
                for (int q = 0; q < 4; ++q) acc[mi][ni][q] = 0.f;

        Ag = An; Bg = Bn;
    }
}

// ============================ routing ======================================
__global__ void logits_kernel(const float* __restrict__ x, const float* __restrict__ Wr) {
    const int t = blockIdx.x;
    const int tid = threadIdx.x;           // 256
    const float* xr = x + (size_t)t * DD;
    float p[8] = {0, 0, 0, 0, 0, 0, 0, 0};
    for (int d = tid; d < DD; d += 256) {
        float xv = xr[d];
        const float4 w0 = *(const float4*)(Wr + d * 8);
        const float4 w1 = *(const float4*)(Wr + d * 8 + 4);
        p[0] += xv * w0.x; p[1] += xv * w0.y; p[2] += xv * w0.z; p[3] += xv * w0.w;
        p[4] += xv * w1.x; p[5] += xv * w1.y; p[6] += xv * w1.z; p[7] += xv * w1.w;
    }
    __shared__ float sm[8][256];
    #pragma unroll
    for (int e = 0; e < 8; ++e) sm[e][tid] = p[e];
    __syncthreads();
    for (int off = 128; off > 0; off >>= 1) {
        if (tid < off) {
            #pragma unroll
            for (int e = 0; e < 8; ++e) sm[e][tid] += sm[e][tid + off];
        }
        __syncthreads();
    }
    if (tid < 8) {
        unsigned k = __float_as_uint(sm[tid][0]);
        k = (k & 0x80000000u) ? ~k : (k | 0x80000000u);
        g_keys[tid * NT + t] = k;
    }
}

__device__ int block_exscan(int v, int* s, int tid) {
    s[tid] = v; __syncthreads();
    for (int d = 1; d < 1024; d <<= 1) {
        int t = (tid >= d) ? s[tid - d] : 0;
        __syncthreads();
        s[tid] += t;
        __syncthreads();
    }
    int inc = s[tid];
    __syncthreads();
    return inc - v;
}

__global__ void select_kernel() {
    const int e = blockIdx.x;
    const int tid = threadIdx.x;           // 1024
    const unsigned* keys = g_keys + e * NT;
    __shared__ unsigned hist[256];
    __shared__ unsigned sh_prefix, sh_R;
    __shared__ int scan[1024];

    unsigned prefix = 0, R = CAPN;
    for (int p = 3; p >= 0; --p) {
        if (tid < 256) hist[tid] = 0u;
        __syncthreads();
        for (int t = tid; t < NT; t += 1024) {
            unsigned k = keys[t];
            if (p == 3 || ((k >> (8 * (p + 1))) == prefix))
                atomicAdd(&hist[(k >> (8 * p)) & 255u], 1u);
        }
        __syncthreads();
        if (tid == 0) {
            unsigned acc = 0; int bsel = 0; unsigned Rn = R;
            for (int v = 255; v >= 0; --v) {
                if (acc + hist[v] >= R) { bsel = v; Rn = R - acc; break; }
                acc += hist[v];
            }
            sh_prefix = (prefix << 8) | (unsigned)bsel;
            sh_R = Rn;
        }
        __syncthreads();
        prefix = sh_prefix; R = sh_R;
        __syncthreads();
    }

    const unsigned Kstar = prefix;
    const int TPT = NT / 1024;             // 16, contiguous per thread
    const int base = tid * TPT;
    int gt = 0, tie = 0;
    for (int i = 0; i < TPT; ++i) {
        unsigned k = keys[base + i];
        gt  += (k > Kstar);
        tie += (k == Kstar);
    }
    int tie_off = block_exscan(tie, scan, tid);
    int take = (int)R - tie_off;
    if (take < 0) take = 0;
    if (take > tie) take = tie;
    int slot_off = block_exscan(gt + take, scan, tid);

    int slot = slot_off, trank = tie_off;
    for (int i = 0; i < TPT; ++i) {
        const int t = base + i;
        const unsigned k = keys[t];
        int s = -1;
        if (k > Kstar)       s = slot++;
        else if (k == Kstar) { if (trank < (int)R) s = slot++; trank++; }
        g_inv[e * NT + t] = s;
        if (s >= 0) g_sel[e * CAPN + s] = t;
    }
}

// ============================ fused prep ===================================
__global__ void prep_kernel(const float* __restrict__ W1,
                            const float* __restrict__ W2,
                            const float* __restrict__ x) {
    const int bid = blockIdx.x;
    const int tid = threadIdx.x;            // 256
    if (bid < 65536) {
        const int which = bid >> 15;        // 0: W1, 1: W2
        const int lb = bid & 32767;
        const int M = which ? FF : DD;
        const int N = which ? DD : FF;
        const int ntile = N / 32;
        const int e  = lb / (ntile * (M / 32));
        const int r  = lb % (ntile * (M / 32));
        const int n0 = (r % ntile) * 32;
        const int m0 = (r / ntile) * 32;
        const float* I = (which ? W2 : W1) + (size_t)e * M * N;
        __half* O = (which ? g_W2t : g_W1t) + (size_t)e * M * N;
        __shared__ float tile[32][33];
        const int tx = tid & 31, ty = tid >> 5;     // ty in [0,8)
        #pragma unroll
        for (int k = 0; k < 32; k += 8)
            tile[ty + k][tx] = I[(size_t)(m0 + ty + k) * N + n0 + tx];
        __syncthreads();
        #pragma unroll
        for (int k = 0; k < 32; k += 8)
            O[(size_t)(n0 + ty + k) * M + m0 + tx] = __float2half(tile[tx][ty + k]);
    } else {
        const int r = (bid - 65536) * 2 + (tid >> 7);   // e*CAPN + slot
        const int lt = tid & 127;
        const int tok = g_sel[r];
        const float* src = x + (size_t)tok * DD;
        __half* dst = g_Xp + (size_t)r * DD;
        float4 a = ((const float4*)src)[lt * 2];
        float4 b = ((const float4*)src)[lt * 2 + 1];
        __half2 h0 = __floats2half2_rn(a.x, a.y);
        __half2 h1 = __floats2half2_rn(a.z, a.w);
        __half2 h2 = __floats2half2_rn(b.x, b.y);
        __half2 h3 = __floats2half2_rn(b.z, b.w);
        uint4 o;
        o.x = *(uint32_t*)&h0; o.y = *(uint32_t*)&h1;
        o.z = *(uint32_t*)&h2; o.w = *(uint32_t*)&h3;
        ((uint4*)dst)[lt] = o;
    }
}

__global__ void combine_kernel(float* __restrict__ out) {
    const int t = blockIdx.x;
    const int tid = threadIdx.x;            // 256, 4 floats each
    __shared__ int inv[8];
    if (tid < 8) inv[tid] = g_inv[tid * NT + t];
    __syncthreads();
    float4 acc = make_float4(0.f, 0.f, 0.f, 0.f);
    #pragma unroll
    for (int e = 0; e < 8; ++e) {
        const int s = inv[e];
        if (s >= 0) {
            const uint2 raw = *(const uint2*)(g_Yh + ((size_t)(e * CAPN + s)) * DD + tid * 4);
            const __half2 y0 = *(const __half2*)&raw.x;
            const __half2 y1 = *(const __half2*)&raw.y;
            float2 f0 = __half22float2(y0);
            float2 f1 = __half22float2(y1);
            acc.x += f0.x; acc.y += f0.y; acc.z += f1.x; acc.w += f1.y;
        }
    }
    *(float4*)(out + (size_t)t * DD + tid * 4) = acc;
}

// ============================ launch =======================================
extern "C" void kernel_launch(void* const* d_in, const int* in_sizes, int n_in,
                              void* d_out, int out_size) {
    (void)in_sizes; (void)n_in; (void)out_size;
    const float* x  = (const float*)d_in[0];
    const float* Wr = (const float*)d_in[1];
    const float* W1 = (const float*)d_in[2];
    const float* b1 = (const float*)d_in[3];
    const float* W2 = (const float*)d_in[4];
    const float* b2 = (const float*)d_in[5];
    float* out = (float*)d_out;

    int smCount = 148, dev = 0;
    cudaGetDevice(&dev);
    cudaDeviceGetAttribute(&smCount, cudaDevAttrMultiProcessorCount, dev);
    const int P = 2 * smCount;              // persistent grid, 2 CTAs/SM

    cudaFuncSetAttribute(gemm_kernel<true>,  cudaFuncAttributeMaxDynamicSharedMemorySize, SMEM_TOTAL);
    cudaFuncSetAttribute(gemm_kernel<false>, cudaFuncAttributeMaxDynamicSharedMemorySize, SMEM_TOTAL);

    // launch order keeps gemm_kernel<true> in the ncu capture slot.
    logits_kernel<<<NT, 256>>>(x, Wr);
    select_kernel<<<NE, 1024>>>();
    prep_kernel<<<65536 + NE * CAPN / 2, 256>>>(W1, W2, x);

    gemm_kernel<true ><<<P, 256, SMEM_TOTAL>>>(b1);
    gemm_kernel<false><<<P, 256, SMEM_TOTAL>>>(b2);

    combine_kernel<<<NT, 256>>>(out);
}

// round 10
// speedup vs baseline: 1.0202x; 1.0202x over previous
#include <cuda_runtime.h>
#include <cuda_fp16.h>
#include <cstdint>
#include <cstddef>
#include <math.h>

#define NE    8
#define DD    1024
#define FF    4096
#define CAPN  4096
#define NT    16384     // B*T tokens

// ----------------------------- static scratch ------------------------------
__device__ unsigned g_keys[NE * NT];
__device__ int      g_sel [NE * CAPN];             // slot -> token
__device__ int      g_inv [NE * NT];               // (e,token) -> slot or -1
__device__ __half   g_W1t[(size_t)NE * FF * DD];   // [e][f][d] K-major
__device__ __half   g_W2t[(size_t)NE * DD * FF];   // [e][d][f] K-major
__device__ __half   g_Xp [(size_t)NE * CAPN * DD]; // gathered tokens fp16
__device__ __half   g_H  [(size_t)NE * CAPN * FF]; // gelu(X@W1+b1) fp16
__device__ __half   g_Yh [(size_t)NE * CAPN * DD]; // H@W2+b2 fp16

// ----------------------------- helpers -------------------------------------
#define DEV __device__ __forceinline__

DEV uint32_t smem_u32(const void* p) {
    uint32_t a;
    asm("{ .reg .u64 t; cvta.to.shared.u64 t, %1; cvt.u32.u64 %0, t; }"
        : "=r"(a) : "l"(p));
    return a;
}

DEV uint32_t sw128(uint32_t off) { return off ^ ((off >> 3) & 0x70); }

DEV void cp16(uint32_t saddr, const void* g) {
    asm volatile("cp.async.cg.shared.global [%0], [%1], 16;" :: "r"(saddr), "l"(g));
}
#define CP_COMMIT() asm volatile("cp.async.commit_group;" ::: "memory")
#define CP_WAIT1()  asm volatile("cp.async.wait_group 1;" ::: "memory")

DEV void ldsm4(uint32_t* r, uint32_t addr) {
    asm volatile("ldmatrix.sync.aligned.m8n8.x4.shared.b16 {%0,%1,%2,%3}, [%4];"
        : "=r"(r[0]), "=r"(r[1]), "=r"(r[2]), "=r"(r[3]) : "r"(addr));
}

DEV void mma16816(float* c, const uint32_t* a, const uint32_t* b) {
    asm volatile("mma.sync.aligned.m16n8k16.row.col.f32.f16.f16.f32 "
        "{%0,%1,%2,%3}, {%4,%5,%6,%7}, {%8,%9}, {%0,%1,%2,%3};"
        : "+f"(c[0]), "+f"(c[1]), "+f"(c[2]), "+f"(c[3])
        : "r"(a[0]), "r"(a[1]), "r"(a[2]), "r"(a[3]), "r"(b[0]), "r"(b[1]));
}

// ----------------------------- GEMM ----------------------------------------
// R7 config (best measured): CTA 128x128, BK=64, 3-stage cp.async, 256 thr
// (8 warps, warp tile 64x32), 2 CTAs/SM.
// R10 micro-opts: strength-reduced cp.async addressing (prologue-computed
// offsets) + chunk-head reorder (kk0 LDSM before cp.async batch).
#define BM 128
#define BN 128
#define BK 64
#define STAGES 3
#define A_BYTES (BM * BK * 2)               // 16384
#define STAGE_BYTES (2 * A_BYTES)           // 32768 (A + B)
#define SM_BIAS (STAGES * STAGE_BYTES)      // 98304
#define SMEM_TOTAL (SM_BIAS + BN * 4)       // 98816

// GELU=true : C=gelu(Xp@W1t^T + b1) -> g_H (fp16), K=1024, N total=4096
// GELU=false: C=H @W2t^T + b2       -> g_Yh (fp16), K=4096, N total=1024
template<bool GELU>
__global__ void __launch_bounds__(256, 2) gemm_kernel(const float* __restrict__ bias) {
    constexpr int K    = GELU ? DD : FF;
    constexpr int NTOT = GELU ? FF : DD;
    constexpr int KT   = K / BK;

    extern __shared__ char smem[];
    const uint32_t sb = smem_u32(smem);
    const int tid = threadIdx.x;
    const int lane = tid & 31, wid = tid >> 5;
    const int wm = wid >> 2, wn = wid & 3;        // warp: 64x32 of 128x128
    const int e  = blockIdx.z;
    const int mt = blockIdx.y;
    const int nt = blockIdx.x;

    const char* Agb = (const char*)((GELU ? g_Xp  : g_H)   + ((size_t)e * CAPN + mt * BM) * K);
    const char* Bgb = (const char*)((GELU ? g_W1t : g_W2t) + ((size_t)e * NTOT + nt * BN) * K);

    if (tid < BN)
        ((float*)(smem + SM_BIAS))[tid] = bias[e * NTOT + nt * BN + tid];

    // precomputed per-thread copy offsets (4 chunks of 16B for A, same for B)
    uint32_t soff[4], goff[4];
    #pragma unroll
    for (int i = 0; i < 4; ++i) {
        int u = tid + i * 256;                    // < 1024
        int row = u >> 3, ch = u & 7;
        soff[i] = sw128(row * 128 + ch * 16);
        goff[i] = (uint32_t)row * (K * 2) + ch * 16;
    }

    auto load_stage = [&](int c, int s) {
        const uint32_t sAb = sb + s * STAGE_BYTES;
        const uint32_t cb  = (uint32_t)c * 128;   // BK*2 bytes
        #pragma unroll
        for (int i = 0; i < 4; ++i)
            cp16(sAb + soff[i], Agb + goff[i] + cb);
        #pragma unroll
        for (int i = 0; i < 4; ++i)
            cp16(sAb + A_BYTES + soff[i], Bgb + goff[i] + cb);
        CP_COMMIT();
    };

    float acc[4][4][4];
    #pragma unroll
    for (int mi = 0; mi < 4; ++mi)
        #pragma unroll
        for (int ni = 0; ni < 4; ++ni)
            #pragma unroll
            for (int q = 0; q < 4; ++q) acc[mi][ni][q] = 0.f;

    load_stage(0, 0);
    load_stage(1, 1);

    // ldmatrix per-lane address components
    const int sel = lane >> 3;
    const int aRow = wm * 64 + (lane & 7) + ((sel & 1) << 3);   // + mi*16
    const int aCh  = sel >> 1;                                   // + 2*kk
    const int bRow = wn * 32 + (lane & 7) + ((sel >> 1) << 3);   // + np*16
    const int bCh  = sel & 1;                                    // + 2*kk

    for (int c = 0; c < KT; ++c) {
        CP_WAIT1();
        __syncthreads();

        const int s = c % STAGES;
        const uint32_t sA = sb + s * STAGE_BYTES;
        const uint32_t sB = sA + A_BYTES;

        // --- kk = 0: LDSM first, slide cp.async batch into its shadow ------
        uint32_t a[4][4];
        uint32_t b[4][2];
        #pragma unroll
        for (int mi = 0; mi < 4; ++mi)
            ldsm4(a[mi], sA + sw128((aRow + mi * 16) * 128 + aCh * 16));
        {
            uint32_t r0[4], r1[4];
            ldsm4(r0, sB + sw128((bRow +  0) * 128 + bCh * 16));
            ldsm4(r1, sB + sw128((bRow + 16) * 128 + bCh * 16));
            b[0][0] = r0[0]; b[0][1] = r0[1]; b[1][0] = r0[2]; b[1][1] = r0[3];
            b[2][0] = r1[0]; b[2][1] = r1[1]; b[3][0] = r1[2]; b[3][1] = r1[3];
        }

        if (c + 2 < KT) load_stage(c + 2, (c + 2) % STAGES);
        else CP_COMMIT();

        #pragma unroll
        for (int mi = 0; mi < 4; ++mi)
            #pragma unroll
            for (int ni = 0; ni < 4; ++ni)
                mma16816(acc[mi][ni], a[mi], b[ni]);

        // --- kk = 1..3 ------------------------------------------------------
        #pragma unroll
        for (int kk = 1; kk < 4; ++kk) {
            #pragma unroll
            for (int mi = 0; mi < 4; ++mi)
                ldsm4(a[mi], sA + sw128((aRow + mi * 16) * 128 + (2 * kk + aCh) * 16));
            #pragma unroll
            for (int np = 0; np < 2; ++np) {
                uint32_t r[4];
                ldsm4(r, sB + sw128((bRow + np * 16) * 128 + (2 * kk + bCh) * 16));
                b[2 * np][0] = r[0]; b[2 * np][1] = r[1];
                b[2 * np + 1][0] = r[2]; b[2 * np + 1][1] = r[3];
            }
            #pragma unroll
            for (int mi = 0; mi < 4; ++mi)
                #pragma unroll
                for (int ni = 0; ni < 4; ++ni)
                    mma16816(acc[mi][ni], a[mi], b[ni]);
        }
    }
    asm volatile("cp.async.wait_all;" ::: "memory");
    __syncthreads();

    // ------------------------------ epilogue -------------------------------
    const float* sbias = (const float*)(smem + SM_BIAS);
    const int g = lane >> 2, i2 = (lane & 3) * 2;
    #pragma unroll
    for (int mi = 0; mi < 4; ++mi) {
        #pragma unroll
        for (int h = 0; h < 2; ++h) {
            const size_t crow = (size_t)e * CAPN + (size_t)mt * BM + wm * 64 + mi * 16 + g + 8 * h;
            #pragma unroll
            for (int ni = 0; ni < 4; ++ni) {
                const int lcol = wn * 32 + ni * 8 + i2;
                float v0 = acc[mi][ni][2 * h + 0] + sbias[lcol + 0];
                float v1 = acc[mi][ni][2 * h + 1] + sbias[lcol + 1];
                if (GELU) {
                    v0 = 0.5f * v0 * (1.0f + erff(v0 * 0.70710678118654752f));
                    v1 = 0.5f * v1 * (1.0f + erff(v1 * 0.70710678118654752f));
                    __half2 h2 = __floats2half2_rn(v0, v1);
                    *(__half2*)(g_H + crow * FF + nt * BN + lcol) = h2;
                } else {
                    __half2 h2 = __floats2half2_rn(v0, v1);
                    *(__half2*)(g_Yh + crow * DD + nt * BN + lcol) = h2;
                }
            }
        }
    }
}

// ============================ routing ======================================
__global__ void logits_kernel(const float* __restrict__ x, const float* __restrict__ Wr) {
    const int t = blockIdx.x;
    const int tid = threadIdx.x;           // 256
    const float* xr = x + (size_t)t * DD;
    float p[8] = {0, 0, 0, 0, 0, 0, 0, 0};
    for (int d = tid; d < DD; d += 256) {
        float xv = xr[d];
        const float4 w0 = *(const float4*)(Wr + d * 8);
        const float4 w1 = *(const float4*)(Wr + d * 8 + 4);
        p[0] += xv * w0.x; p[1] += xv * w0.y; p[2] += xv * w0.z; p[3] += xv * w0.w;
        p[4] += xv * w1.x; p[5] += xv * w1.y; p[6] += xv * w1.z; p[7] += xv * w1.w;
    }
    __shared__ float sm[8][256];
    #pragma unroll
    for (int e = 0; e < 8; ++e) sm[e][tid] = p[e];
    __syncthreads();
    for (int off = 128; off > 0; off >>= 1) {
        if (tid < off) {
            #pragma unroll
            for (int e = 0; e < 8; ++e) sm[e][tid] += sm[e][tid + off];
        }
        __syncthreads();
    }
    if (tid < 8) {
        unsigned k = __float_as_uint(sm[tid][0]);
        k = (k & 0x80000000u) ? ~k : (k | 0x80000000u);
        g_keys[tid * NT + t] = k;
    }
}

__device__ int block_exscan(int v, int* s, int tid) {
    s[tid] = v; __syncthreads();
    for (int d = 1; d < 1024; d <<= 1) {
        int t = (tid >= d) ? s[tid - d] : 0;
        __syncthreads();
        s[tid] += t;
        __syncthreads();
    }
    int inc = s[tid];
    __syncthreads();
    return inc - v;
}

__global__ void select_kernel() {
    const int e = blockIdx.x;
    const int tid = threadIdx.x;           // 1024
    const unsigned* keys = g_keys + e * NT;
    __shared__ unsigned hist[256];
    __shared__ unsigned sh_prefix, sh_R;
    __shared__ int scan[1024];

    unsigned prefix = 0, R = CAPN;
    for (int p = 3; p >= 0; --p) {
        if (tid < 256) hist[tid] = 0u;
        __syncthreads();
        for (int t = tid; t < NT; t += 1024) {
            unsigned k = keys[t];
            if (p == 3 || ((k >> (8 * (p + 1))) == prefix))
                atomicAdd(&hist[(k >> (8 * p)) & 255u], 1u);
        }
        __syncthreads();
        if (tid == 0) {
            unsigned acc = 0; int bsel = 0; unsigned Rn = R;
            for (int v = 255; v >= 0; --v) {
                if (acc + hist[v] >= R) { bsel = v; Rn = R - acc; break; }
                acc += hist[v];
            }
            sh_prefix = (prefix << 8) | (unsigned)bsel;
            sh_R = Rn;
        }
        __syncthreads();
        prefix = sh_prefix; R = sh_R;
        __syncthreads();
    }

    const unsigned Kstar = prefix;
    const int TPT = NT / 1024;             // 16, contiguous per thread
    const int base = tid * TPT;
    int gt = 0, tie = 0;
    for (int i = 0; i < TPT; ++i) {
        unsigned k = keys[base + i];
        gt  += (k > Kstar);
        tie += (k == Kstar);
    }
    int tie_off = block_exscan(tie, scan, tid);
    int take = (int)R - tie_off;
    if (take < 0) take = 0;
    if (take > tie) take = tie;
    int slot_off = block_exscan(gt + take, scan, tid);

    int slot = slot_off, trank = tie_off;
    for (int i = 0; i < TPT; ++i) {
        const int t = base + i;
        const unsigned k = keys[t];
        int s = -1;
        if (k > Kstar)       s = slot++;
        else if (k == Kstar) { if (trank < (int)R) s = slot++; trank++; }
        g_inv[e * NT + t] = s;
        if (s >= 0) g_sel[e * CAPN + s] = t;
    }
}

// ============================ fused prep ===================================
__global__ void prep_kernel(const float* __restrict__ W1,
                            const float* __restrict__ W2,
                            const float* __restrict__ x) {
    const int bid = blockIdx.x;
    const int tid = threadIdx.x;            // 256
    if (bid < 65536) {
        const int which = bid >> 15;        // 0: W1, 1: W2
        const int lb = bid & 32767;
        const int M = which ? FF : DD;
        const int N = which ? DD : FF;
        const int ntile = N / 32;
        const int e  = lb / (ntile * (M / 32));
        const int r  = lb % (ntile * (M / 32));
        const int n0 = (r % ntile) * 32;
        const int m0 = (r / ntile) * 32;
        const float* I = (which ? W2 : W1) + (size_t)e * M * N;
        __half* O = (which ? g_W2t : g_W1t) + (size_t)e * M * N;
        __shared__ float tile[32][33];
        const int tx = tid & 31, ty = tid >> 5;     // ty in [0,8)
        #pragma unroll
        for (int k = 0; k < 32; k += 8)
            tile[ty + k][tx] = I[(size_t)(m0 + ty + k) * N + n0 + tx];
        __syncthreads();
        #pragma unroll
        for (int k = 0; k < 32; k += 8)
            O[(size_t)(n0 + ty + k) * M + m0 + tx] = __float2half(tile[tx][ty + k]);
    } else {
        const int r = (bid - 65536) * 2 + (tid >> 7);   // e*CAPN + slot
        const int lt = tid & 127;
        const int tok = g_sel[r];
        const float* src = x + (size_t)tok * DD;
        __half* dst = g_Xp + (size_t)r * DD;
        float4 a = ((const float4*)src)[lt * 2];
        float4 b = ((const float4*)src)[lt * 2 + 1];
        __half2 h0 = __floats2half2_rn(a.x, a.y);
        __half2 h1 = __floats2half2_rn(a.z, a.w);
        __half2 h2 = __floats2half2_rn(b.x, b.y);
        __half2 h3 = __floats2half2_rn(b.z, b.w);
        uint4 o;
        o.x = *(uint32_t*)&h0; o.y = *(uint32_t*)&h1;
        o.z = *(uint32_t*)&h2; o.w = *(uint32_t*)&h3;
        ((uint4*)dst)[lt] = o;
    }
}

__global__ void combine_kernel(float* __restrict__ out) {
    const int t = blockIdx.x;
    const int tid = threadIdx.x;            // 256, 4 floats each
    __shared__ int inv[8];
    if (tid < 8) inv[tid] = g_inv[tid * NT + t];
    __syncthreads();
    float4 acc = make_float4(0.f, 0.f, 0.f, 0.f);
    #pragma unroll
    for (int e = 0; e < 8; ++e) {
        const int s = inv[e];
        if (s >= 0) {
            const uint2 raw = *(const uint2*)(g_Yh + ((size_t)(e * CAPN + s)) * DD + tid * 4);
            const __half2 y0 = *(const __half2*)&raw.x;
            const __half2 y1 = *(const __half2*)&raw.y;
            float2 f0 = __half22float2(y0);
            float2 f1 = __half22float2(y1);
            acc.x += f0.x; acc.y += f0.y; acc.z += f1.x; acc.w += f1.y;
        }
    }
    *(float4*)(out + (size_t)t * DD + tid * 4) = acc;
}

// ============================ launch =======================================
extern "C" void kernel_launch(void* const* d_in, const int* in_sizes, int n_in,
                              void* d_out, int out_size) {
    (void)in_sizes; (void)n_in; (void)out_size;
    const float* x  = (const float*)d_in[0];
    const float* Wr = (const float*)d_in[1];
    const float* W1 = (const float*)d_in[2];
    const float* b1 = (const float*)d_in[3];
    const float* W2 = (const float*)d_in[4];
    const float* b2 = (const float*)d_in[5];
    float* out = (float*)d_out;

    cudaFuncSetAttribute(gemm_kernel<true>,  cudaFuncAttributeMaxDynamicSharedMemorySize, SMEM_TOTAL);
    cudaFuncSetAttribute(gemm_kernel<false>, cudaFuncAttributeMaxDynamicSharedMemorySize, SMEM_TOTAL);

    // launch order keeps gemm_kernel<true> in the ncu capture slot.
    logits_kernel<<<NT, 256>>>(x, Wr);
    select_kernel<<<NE, 1024>>>();
    prep_kernel<<<65536 + NE * CAPN / 2, 256>>>(W1, W2, x);

    gemm_kernel<true ><<<dim3(FF / BN, CAPN / BM, NE), 256, SMEM_TOTAL>>>(b1);
    gemm_kernel<false><<<dim3(DD / BN, CAPN / BM, NE), 256, SMEM_TOTAL>>>(b2);

    combine_kernel<<<NT, 256>>>(out);
}

// round 11
// speedup vs baseline: 1.0982x; 1.0765x over previous
#include <cuda_runtime.h>
#include <cuda_fp16.h>
#include <cstdint>
#include <cstddef>
#include <math.h>

#define NE    8
#define DD    1024
#define FF    4096
#define CAPN  4096
#define NT    16384     // B*T tokens

// ----------------------------- static scratch ------------------------------
__device__ unsigned g_keys[NE * NT];
__device__ int      g_sel [NE * CAPN];             // slot -> token
__device__ int      g_inv [NE * NT];               // (e,token) -> slot or -1
__device__ __half   g_W1t[(size_t)NE * FF * DD];   // [e][f][d] K-major
__device__ __half   g_W2t[(size_t)NE * DD * FF];   // [e][d][f] K-major
__device__ __half   g_Xp [(size_t)NE * CAPN * DD]; // gathered tokens fp16
__device__ __half   g_H  [(size_t)NE * CAPN * FF]; // gelu(X@W1+b1) fp16
__device__ __half   g_Yh [(size_t)NE * CAPN * DD]; // H@W2+b2 fp16

// ----------------------------- helpers -------------------------------------
#define DEV __device__ __forceinline__

DEV uint32_t smem_u32(const void* p) {
    uint32_t a;
    asm("{ .reg .u64 t; cvta.to.shared.u64 t, %1; cvt.u32.u64 %0, t; }"
        : "=r"(a) : "l"(p));
    return a;
}

DEV uint32_t sw128(uint32_t off) { return off ^ ((off >> 3) & 0x70); }

DEV void cp16(uint32_t saddr, const void* g) {
    asm volatile("cp.async.cg.shared.global [%0], [%1], 16;" :: "r"(saddr), "l"(g));
}
#define CP_COMMIT() asm volatile("cp.async.commit_group;" ::: "memory")
#define CP_WAIT1()  asm volatile("cp.async.wait_group 1;" ::: "memory")

DEV void ldsm4(uint32_t* r, uint32_t addr) {
    asm volatile("ldmatrix.sync.aligned.m8n8.x4.shared.b16 {%0,%1,%2,%3}, [%4];"
        : "=r"(r[0]), "=r"(r[1]), "=r"(r[2]), "=r"(r[3]) : "r"(addr));
}

DEV void mma16816(float* c, const uint32_t* a, const uint32_t* b) {
    asm volatile("mma.sync.aligned.m16n8k16.row.col.f32.f16.f16.f32 "
        "{%0,%1,%2,%3}, {%4,%5,%6,%7}, {%8,%9}, {%0,%1,%2,%3};"
        : "+f"(c[0]), "+f"(c[1]), "+f"(c[2]), "+f"(c[3])
        : "r"(a[0]), "r"(a[1]), "r"(a[2]), "r"(a[3]), "r"(b[0]), "r"(b[1]));
}

// ----------------------------- GEMM ----------------------------------------
// R7 config (best measured, byte-exact revert): CTA 128x128, BK=64, 3-stage
// cp.async, 256 thr (8 warps, warp tile 64x32), 2 CTAs/SM.
#define BM 128
#define BN 128
#define BK 64
#define STAGES 3
#define A_BYTES (BM * BK * 2)               // 16384
#define STAGE_BYTES (2 * A_BYTES)           // 32768 (A + B)
#define SM_BIAS (STAGES * STAGE_BYTES)      // 98304
#define SMEM_TOTAL (SM_BIAS + BN * 4)       // 98816

// GELU=true : C=gelu(Xp@W1t^T + b1) -> g_H (fp16), K=1024, N total=4096
// GELU=false: C=H @W2t^T + b2       -> g_Yh (fp16), K=4096, N total=1024
template<bool GELU>
__global__ void __launch_bounds__(256, 2) gemm_kernel(const float* __restrict__ bias) {
    constexpr int K    = GELU ? DD : FF;
    constexpr int NTOT = GELU ? FF : DD;
    constexpr int KT   = K / BK;

    extern __shared__ char smem[];
    const uint32_t sb = smem_u32(smem);
    const int tid = threadIdx.x;
    const int lane = tid & 31, wid = tid >> 5;
    const int wm = wid >> 2, wn = wid & 3;        // warp: 64x32 of 128x128
    const int e  = blockIdx.z;
    const int mt = blockIdx.y;
    const int nt = blockIdx.x;

    const __half* Ag = (GELU ? g_Xp  : g_H)   + ((size_t)e * CAPN + mt * BM) * K;
    const __half* Bg = (GELU ? g_W1t : g_W2t) + ((size_t)e * NTOT + nt * BN) * K;

    if (tid < BN)
        ((float*)(smem + SM_BIAS))[tid] = bias[e * NTOT + nt * BN + tid];

    // per-stage loads: 1024 A-chunks + 1024 B-chunks of 16B; 8 per thread
    auto load_stage = [&](int c, int s) {
        const uint32_t sAb = sb + s * STAGE_BYTES;
        const uint32_t sBb = sAb + A_BYTES;
        const __half* As = Ag + c * BK;
        const __half* Bs = Bg + c * BK;
        #pragma unroll
        for (int i = 0; i < 4; ++i) {
            int u = tid + i * 256;                 // < 1024
            int row = u >> 3, ch = u & 7;
            cp16(sAb + sw128(row * 128 + ch * 16), As + (size_t)row * K + ch * 8);
        }
        #pragma unroll
        for (int i = 0; i < 4; ++i) {
            int u = tid + i * 256;
            int row = u >> 3, ch = u & 7;
            cp16(sBb + sw128(row * 128 + ch * 16), Bs + (size_t)row * K + ch * 8);
        }
        CP_COMMIT();
    };

    float acc[4][4][4];
    #pragma unroll
    for (int mi = 0; mi < 4; ++mi)
        #pragma unroll
        for (int ni = 0; ni < 4; ++ni)
            #pragma unroll
            for (int q = 0; q < 4; ++q) acc[mi][ni][q] = 0.f;

    load_stage(0, 0);
    load_stage(1, 1);

    // ldmatrix per-lane address components
    const int sel = lane >> 3;
    const int aRow = wm * 64 + (lane & 7) + ((sel & 1) << 3);   // + mi*16
    const int aCh  = sel >> 1;                                   // + 2*kk
    const int bRow = wn * 32 + (lane & 7) + ((sel >> 1) << 3);   // + np*16
    const int bCh  = sel & 1;                                    // + 2*kk

    for (int c = 0; c < KT; ++c) {
        CP_WAIT1();
        __syncthreads();
        if (c + STAGES - 1 < KT) load_stage(c + STAGES - 1, (c + STAGES - 1) % STAGES);
        else CP_COMMIT();

        const int s = c % STAGES;
        const uint32_t sA = sb + s * STAGE_BYTES;
        const uint32_t sB = sA + A_BYTES;

        #pragma unroll
        for (int kk = 0; kk < 4; ++kk) {
            uint32_t a[4][4];
            #pragma unroll
            for (int mi = 0; mi < 4; ++mi)
                ldsm4(a[mi], sA + sw128((aRow + mi * 16) * 128 + (2 * kk + aCh) * 16));
            uint32_t b[4][2];
            #pragma unroll
            for (int np = 0; np < 2; ++np) {
                uint32_t r[4];
                ldsm4(r, sB + sw128((bRow + np * 16) * 128 + (2 * kk + bCh) * 16));
                b[2 * np][0] = r[0]; b[2 * np][1] = r[1];
                b[2 * np + 1][0] = r[2]; b[2 * np + 1][1] = r[3];
            }
            #pragma unroll
            for (int mi = 0; mi < 4; ++mi)
                #pragma unroll
                for (int ni = 0; ni < 4; ++ni)
                    mma16816(acc[mi][ni], a[mi], b[ni]);
        }
    }
    asm volatile("cp.async.wait_all;" ::: "memory");
    __syncthreads();

    // ------------------------------ epilogue -------------------------------
    const float* sbias = (const float*)(smem + SM_BIAS);
    const int g = lane >> 2, i2 = (lane & 3) * 2;
    #pragma unroll
    for (int mi = 0; mi < 4; ++mi) {
        #pragma unroll
        for (int h = 0; h < 2; ++h) {
            const size_t crow = (size_t)e * CAPN + (size_t)mt * BM + wm * 64 + mi * 16 + g + 8 * h;
            #pragma unroll
            for (int ni = 0; ni < 4; ++ni) {
                const int lcol = wn * 32 + ni * 8 + i2;
                float v0 = acc[mi][ni][2 * h + 0] + sbias[lcol + 0];
                float v1 = acc[mi][ni][2 * h + 1] + sbias[lcol + 1];
                if (GELU) {
                    v0 = 0.5f * v0 * (1.0f + erff(v0 * 0.70710678118654752f));
                    v1 = 0.5f * v1 * (1.0f + erff(v1 * 0.70710678118654752f));
                    __half2 h2 = __floats2half2_rn(v0, v1);
                    *(__half2*)(g_H + crow * FF + nt * BN + lcol) = h2;
                } else {
                    __half2 h2 = __floats2half2_rn(v0, v1);
                    *(__half2*)(g_Yh + crow * DD + nt * BN + lcol) = h2;
                }
            }
        }
    }
}

// ============================ routing ======================================
__global__ void logits_kernel(const float* __restrict__ x, const float* __restrict__ Wr) {
    const int t = blockIdx.x;
    const int tid = threadIdx.x;           // 256
    const float* xr = x + (size_t)t * DD;
    float p[8] = {0, 0, 0, 0, 0, 0, 0, 0};
    for (int d = tid; d < DD; d += 256) {
        float xv = xr[d];
        const float4 w0 = *(const float4*)(Wr + d * 8);
        const float4 w1 = *(const float4*)(Wr + d * 8 + 4);
        p[0] += xv * w0.x; p[1] += xv * w0.y; p[2] += xv * w0.z; p[3] += xv * w0.w;
        p[4] += xv * w1.x; p[5] += xv * w1.y; p[6] += xv * w1.z; p[7] += xv * w1.w;
    }
    __shared__ float sm[8][256];
    #pragma unroll
    for (int e = 0; e < 8; ++e) sm[e][tid] = p[e];
    __syncthreads();
    for (int off = 128; off > 0; off >>= 1) {
        if (tid < off) {
            #pragma unroll
            for (int e = 0; e < 8; ++e) sm[e][tid] += sm[e][tid + off];
        }
        __syncthreads();
    }
    if (tid < 8) {
        unsigned k = __float_as_uint(sm[tid][0]);
        k = (k & 0x80000000u) ? ~k : (k | 0x80000000u);
        g_keys[tid * NT + t] = k;
    }
}

// shfl-based exclusive scan over 1024 threads (2 barriers instead of ~20)
__device__ int block_exscan(int v, int* warpsums, int tid) {
    const int lane = tid & 31, w = tid >> 5;      // 32 warps
    int s = v;
    #pragma unroll
    for (int d = 1; d < 32; d <<= 1) {
        int t = __shfl_up_sync(0xFFFFFFFFu, s, d);
        if (lane >= d) s += t;
    }
    if (lane == 31) warpsums[w] = s;
    __syncthreads();
    if (w == 0) {
        int ws = warpsums[lane];
        #pragma unroll
        for (int d = 1; d < 32; d <<= 1) {
            int t = __shfl_up_sync(0xFFFFFFFFu, ws, d);
            if (lane >= d) ws += t;
        }
        warpsums[lane] = ws;
    }
    __syncthreads();
    const int base = (w > 0) ? warpsums[w - 1] : 0;
    return base + s - v;
}

__global__ void select_kernel() {
    const int e = blockIdx.x;
    const int tid = threadIdx.x;           // 1024
    const unsigned* keys = g_keys + e * NT;
    __shared__ unsigned hist[256];
    __shared__ unsigned sh_prefix, sh_R;
    __shared__ int scan[32];

    unsigned prefix = 0, R = CAPN;
    for (int p = 3; p >= 0; --p) {
        if (tid < 256) hist[tid] = 0u;
        __syncthreads();
        for (int t = tid; t < NT; t += 1024) {
            unsigned k = keys[t];
            if (p == 3 || ((k >> (8 * (p + 1))) == prefix))
                atomicAdd(&hist[(k >> (8 * p)) & 255u], 1u);
        }
        __syncthreads();
        if (tid == 0) {
            unsigned acc = 0; int bsel = 0; unsigned Rn = R;
            for (int v = 255; v >= 0; --v) {
                if (acc + hist[v] >= R) { bsel = v; Rn = R - acc; break; }
                acc += hist[v];
            }
            sh_prefix = (prefix << 8) | (unsigned)bsel;
            sh_R = Rn;
        }
        __syncthreads();
        prefix = sh_prefix; R = sh_R;
        __syncthreads();
    }

    const unsigned Kstar = prefix;
    const int TPT = NT / 1024;             // 16, contiguous per thread
    const int base = tid * TPT;
    int gt = 0, tie = 0;
    for (int i = 0; i < TPT; ++i) {
        unsigned k = keys[base + i];
        gt  += (k > Kstar);
        tie += (k == Kstar);
    }
    int tie_off = block_exscan(tie, scan, tid);
    int take = (int)R - tie_off;
    if (take < 0) take = 0;
    if (take > tie) take = tie;
    int slot_off = block_exscan(gt + take, scan, tid);

    int slot = slot_off, trank = tie_off;
    for (int i = 0; i < TPT; ++i) {
        const int t = base + i;
        const unsigned k = keys[t];
        int s = -1;
        if (k > Kstar)       s = slot++;
        else if (k == Kstar) { if (trank < (int)R) s = slot++; trank++; }
        g_inv[e * NT + t] = s;
        if (s >= 0) g_sel[e * CAPN + s] = t;
    }
}

// ============================ fused prep ===================================
// transpose tiles are 64(m) x 32(n): reads AND writes both 128B-coalesced.
//   W1: per expert [D][F] -> [F][D] : 16 mtile * 128 ntile * 8 = 16384 blocks
//   W2: per expert [F][D] -> [D][F] : 64 mtile * 32 ntile * 8  = 16384 blocks
//   gather: 16384 blocks (2 rows each)
#define PREP_W1_BLOCKS (NE * (DD / 64) * (FF / 32))   // 16384
#define PREP_W2_BLOCKS (NE * (FF / 64) * (DD / 32))   // 16384
#define PREP_GATHER_OFF (PREP_W1_BLOCKS + PREP_W2_BLOCKS)
__global__ void prep_kernel(const float* __restrict__ W1,
                            const float* __restrict__ W2,
                            const float* __restrict__ x) {
    const int bid = blockIdx.x;
    const int tid = threadIdx.x;            // 256
    if (bid < PREP_GATHER_OFF) {
        const int which = (bid >= PREP_W1_BLOCKS);
        const int lb = which ? (bid - PREP_W1_BLOCKS) : bid;
        const int M = which ? FF : DD;      // source rows (m)
        const int N = which ? DD : FF;      // source cols (n)
        const int ntile = N / 32;
        const int per_e = (M / 64) * ntile;
        const int e  = lb / per_e;
        const int r  = lb % per_e;
        const int n0 = (r % ntile) * 32;
        const int m0 = (r / ntile) * 64;
        const float* I = (which ? W2 : W1) + (size_t)e * M * N;
        __half* O = (which ? g_W2t : g_W1t) + (size_t)e * M * N;
        __shared__ float tile[64][33];
        {   // read: 64 rows x 32 cols, rows 8 at a time
            const int tx = tid & 31, ty = tid >> 5;         // ty in [0,8)
            #pragma unroll
            for (int k = 0; k < 64; k += 8)
                tile[ty + k][tx] = I[(size_t)(m0 + ty + k) * N + n0 + tx];
        }
        __syncthreads();
        {   // write: 32 out-rows (n) x 64 out-cols (m), n 4 at a time
            const int tx = tid & 63, ty = tid >> 6;         // ty in [0,4)
            #pragma unroll
            for (int k = 0; k < 32; k += 4)
                O[(size_t)(n0 + ty + k) * M + m0 + tx] = __float2half(tile[tx][ty + k]);
        }
    } else {
        const int r = (bid - PREP_GATHER_OFF) * 2 + (tid >> 7);   // e*CAPN + slot
        const int lt = tid & 127;
        const int tok = g_sel[r];
        const float* src = x + (size_t)tok * DD;
        __half* dst = g_Xp + (size_t)r * DD;
        float4 a = ((const float4*)src)[lt * 2];
        float4 b = ((const float4*)src)[lt * 2 + 1];
        __half2 h0 = __floats2half2_rn(a.x, a.y);
        __half2 h1 = __floats2half2_rn(a.z, a.w);
        __half2 h2 = __floats2half2_rn(b.x, b.y);
        __half2 h3 = __floats2half2_rn(b.z, b.w);
        uint4 o;
        o.x = *(uint32_t*)&h0; o.y = *(uint32_t*)&h1;
        o.z = *(uint32_t*)&h2; o.w = *(uint32_t*)&h3;
        ((uint4*)dst)[lt] = o;
    }
}

__global__ void combine_kernel(float* __restrict__ out) {
    const int t = blockIdx.x;
    const int tid = threadIdx.x;            // 256, 4 floats each
    __shared__ int inv[8];
    if (tid < 8) inv[tid] = g_inv[tid * NT + t];
    __syncthreads();
    float4 acc = make_float4(0.f, 0.f, 0.f, 0.f);
    #pragma unroll
    for (int e = 0; e < 8; ++e) {
        const int s = inv[e];
        if (s >= 0) {
            const uint2 raw = *(const uint2*)(g_Yh + ((size_t)(e * CAPN + s)) * DD + tid * 4);
            const __half2 y0 = *(const __half2*)&raw.x;
            const __half2 y1 = *(const __half2*)&raw.y;
            float2 f0 = __half22float2(y0);
            float2 f1 = __half22float2(y1);
            acc.x += f0.x; acc.y += f0.y; acc.z += f1.x; acc.w += f1.y;
        }
    }
    *(float4*)(out + (size_t)t * DD + tid * 4) = acc;
}

// ============================ launch =======================================
extern "C" void kernel_launch(void* const* d_in, const int* in_sizes, int n_in,
                              void* d_out, int out_size) {
    (void)in_sizes; (void)n_in; (void)out_size;
    const float* x  = (const float*)d_in[0];
    const float* Wr = (const float*)d_in[1];
    const float* W1 = (const float*)d_in[2];
    const float* b1 = (const float*)d_in[3];
    const float* W2 = (const float*)d_in[4];
    const float* b2 = (const float*)d_in[5];
    float* out = (float*)d_out;

    cudaFuncSetAttribute(gemm_kernel<true>,  cudaFuncAttributeMaxDynamicSharedMemorySize, SMEM_TOTAL);
    cudaFuncSetAttribute(gemm_kernel<false>, cudaFuncAttributeMaxDynamicSharedMemorySize, SMEM_TOTAL);

    // launch order keeps gemm_kernel<true> in the ncu capture slot.
    logits_kernel<<<NT, 256>>>(x, Wr);
    select_kernel<<<NE, 1024>>>();
    prep_kernel<<<PREP_GATHER_OFF + NE * CAPN / 2, 256>>>(W1, W2, x);

    gemm_kernel<true ><<<dim3(FF / BN, CAPN / BM, NE), 256, SMEM_TOTAL>>>(b1);
    gemm_kernel<false><<<dim3(DD / BN, CAPN / BM, NE), 256, SMEM_TOTAL>>>(b2);

    combine_kernel<<<NT, 256>>>(out);
}

// round 12
// speedup vs baseline: 1.1060x; 1.0071x over previous
#include <cuda_runtime.h>
#include <cuda_fp16.h>
#include <cstdint>
#include <cstddef>
#include <math.h>

#define NE    8
#define DD    1024
#define FF    4096
#define CAPN  4096
#define NT    16384     // B*T tokens

// ----------------------------- static scratch ------------------------------
__device__ unsigned g_keys[NE * NT];
__device__ int      g_sel [NE * CAPN];             // slot -> token
__device__ int      g_inv [NE * NT];               // (e,token) -> slot or -1
__device__ __half   g_W1t[(size_t)NE * FF * DD];   // [e][f][d] K-major
__device__ __half   g_W2t[(size_t)NE * DD * FF];   // [e][d][f] K-major
__device__ __half   g_Xp [(size_t)NE * CAPN * DD]; // gathered tokens fp16
__device__ __half   g_H  [(size_t)NE * CAPN * FF]; // gelu(X@W1+b1) fp16
__device__ __half   g_Yh [(size_t)NE * CAPN * DD]; // H@W2+b2 fp16

// ----------------------------- helpers -------------------------------------
#define DEV __device__ __forceinline__

DEV uint32_t smem_u32(const void* p) {
    uint32_t a;
    asm("{ .reg .u64 t; cvta.to.shared.u64 t, %1; cvt.u32.u64 %0, t; }"
        : "=r"(a) : "l"(p));
    return a;
}

DEV uint32_t sw128(uint32_t off) { return off ^ ((off >> 3) & 0x70); }

DEV void cp16(uint32_t saddr, const void* g) {
    asm volatile("cp.async.cg.shared.global [%0], [%1], 16;" :: "r"(saddr), "l"(g));
}
#define CP_COMMIT() asm volatile("cp.async.commit_group;" ::: "memory")
#define CP_WAIT1()  asm volatile("cp.async.wait_group 1;" ::: "memory")

DEV void ldsm4(uint32_t* r, uint32_t addr) {
    asm volatile("ldmatrix.sync.aligned.m8n8.x4.shared.b16 {%0,%1,%2,%3}, [%4];"
        : "=r"(r[0]), "=r"(r[1]), "=r"(r[2]), "=r"(r[3]) : "r"(addr));
}

DEV void mma16816(float* c, const uint32_t* a, const uint32_t* b) {
    asm volatile("mma.sync.aligned.m16n8k16.row.col.f32.f16.f16.f32 "
        "{%0,%1,%2,%3}, {%4,%5,%6,%7}, {%8,%9}, {%0,%1,%2,%3};"
        : "+f"(c[0]), "+f"(c[1]), "+f"(c[2]), "+f"(c[3])
        : "r"(a[0]), "r"(a[1]), "r"(a[2]), "r"(a[3]), "r"(b[0]), "r"(b[1]));
}

// ----------------------------- GEMM ----------------------------------------
// R12: CTA 128x128, BK=64, 3-stage cp.async, **128 threads (4 warps, warp
// tile 64x64)**, 2 CTAs/SM. Halves smem-read redundancy (A x2, B x2 = 64KB
// per chunk vs 96KB) -> smem-BW ceiling moves from 67% to ~100% of HMMA issue.
#define BM 128
#define BN 128
#define BK 64
#define GTHREADS 128
#define STAGES 3
#define A_BYTES (BM * BK * 2)               // 16384
#define STAGE_BYTES (2 * A_BYTES)           // 32768 (A + B)
#define SM_BIAS (STAGES * STAGE_BYTES)      // 98304
#define SMEM_TOTAL (SM_BIAS + BN * 4)       // 98816 (x2 CTA = 197632 <= 228KB)

// GELU=true : C=gelu(Xp@W1t^T + b1) -> g_H (fp16), K=1024, N total=4096
// GELU=false: C=H @W2t^T + b2       -> g_Yh (fp16), K=4096, N total=1024
template<bool GELU>
__global__ void __launch_bounds__(GTHREADS, 2) gemm_kernel(const float* __restrict__ bias) {
    constexpr int K    = GELU ? DD : FF;
    constexpr int NTOT = GELU ? FF : DD;
    constexpr int KT   = K / BK;

    extern __shared__ char smem[];
    const uint32_t sb = smem_u32(smem);
    const int tid = threadIdx.x;
    const int lane = tid & 31, wid = tid >> 5;
    const int wm = wid >> 1, wn = wid & 1;        // 2x2 warps: 64x64 tiles
    const int e  = blockIdx.z;
    const int mt = blockIdx.y;
    const int nt = blockIdx.x;

    const __half* Ag = (GELU ? g_Xp  : g_H)   + ((size_t)e * CAPN + mt * BM) * K;
    const __half* Bg = (GELU ? g_W1t : g_W2t) + ((size_t)e * NTOT + nt * BN) * K;

    ((float*)(smem + SM_BIAS))[tid] = bias[e * NTOT + nt * BN + tid];

    // per-stage loads: 1024 A-chunks + 1024 B-chunks of 16B; 16 per thread
    auto load_stage = [&](int c, int s) {
        const uint32_t sAb = sb + s * STAGE_BYTES;
        const uint32_t sBb = sAb + A_BYTES;
        const __half* As = Ag + c * BK;
        const __half* Bs = Bg + c * BK;
        #pragma unroll
        for (int i = 0; i < 8; ++i) {
            int u = tid + i * GTHREADS;            // < 1024
            int row = u >> 3, ch = u & 7;
            cp16(sAb + sw128(row * 128 + ch * 16), As + (size_t)row * K + ch * 8);
        }
        #pragma unroll
        for (int i = 0; i < 8; ++i) {
            int u = tid + i * GTHREADS;
            int row = u >> 3, ch = u & 7;
            cp16(sBb + sw128(row * 128 + ch * 16), Bs + (size_t)row * K + ch * 8);
        }
        CP_COMMIT();
    };

    float acc[4][8][4];
    #pragma unroll
    for (int mi = 0; mi < 4; ++mi)
        #pragma unroll
        for (int ni = 0; ni < 8; ++ni)
            #pragma unroll
            for (int q = 0; q < 4; ++q) acc[mi][ni][q] = 0.f;

    load_stage(0, 0);
    load_stage(1, 1);

    // ldmatrix per-lane address components
    const int sel = lane >> 3;
    const int aRow = wm * 64 + (lane & 7) + ((sel & 1) << 3);   // + mi*16
    const int aCh  = sel >> 1;                                   // + 2*kk
    const int bRow = wn * 64 + (lane & 7) + ((sel >> 1) << 3);   // + np*16
    const int bCh  = sel & 1;                                    // + 2*kk

    for (int c = 0; c < KT; ++c) {
        CP_WAIT1();
        __syncthreads();
        if (c + STAGES - 1 < KT) load_stage(c + STAGES - 1, (c + STAGES - 1) % STAGES);
        else CP_COMMIT();

        const int s = c % STAGES;
        const uint32_t sA = sb + s * STAGE_BYTES;
        const uint32_t sB = sA + A_BYTES;

        #pragma unroll
        for (int kk = 0; kk < 4; ++kk) {
            uint32_t a[4][4];
            #pragma unroll
            for (int mi = 0; mi < 4; ++mi)
                ldsm4(a[mi], sA + sw128((aRow + mi * 16) * 128 + (2 * kk + aCh) * 16));
            uint32_t b[8][2];
            #pragma unroll
            for (int np = 0; np < 4; ++np) {
                uint32_t r[4];
                ldsm4(r, sB + sw128((bRow + np * 16) * 128 + (2 * kk + bCh) * 16));
                b[2 * np][0] = r[0]; b[2 * np][1] = r[1];
                b[2 * np + 1][0] = r[2]; b[2 * np + 1][1] = r[3];
            }
            #pragma unroll
            for (int mi = 0; mi < 4; ++mi)
                #pragma unroll
                for (int ni = 0; ni < 8; ++ni)
                    mma16816(acc[mi][ni], a[mi], b[ni]);
        }
    }
    asm volatile("cp.async.wait_all;" ::: "memory");
    __syncthreads();

    // ------------------------------ epilogue -------------------------------
    const float* sbias = (const float*)(smem + SM_BIAS);
    const int g = lane >> 2, i2 = (lane & 3) * 2;
    #pragma unroll
    for (int mi = 0; mi < 4; ++mi) {
        #pragma unroll
        for (int h = 0; h < 2; ++h) {
            const size_t crow = (size_t)e * CAPN + (size_t)mt * BM + wm * 64 + mi * 16 + g + 8 * h;
            #pragma unroll
            for (int ni = 0; ni < 8; ++ni) {
                const int lcol = wn * 64 + ni * 8 + i2;
                float v0 = acc[mi][ni][2 * h + 0] + sbias[lcol + 0];
                float v1 = acc[mi][ni][2 * h + 1] + sbias[lcol + 1];
                if (GELU) {
                    v0 = 0.5f * v0 * (1.0f + erff(v0 * 0.70710678118654752f));
                    v1 = 0.5f * v1 * (1.0f + erff(v1 * 0.70710678118654752f));
                    __half2 h2 = __floats2half2_rn(v0, v1);
                    *(__half2*)(g_H + crow * FF + nt * BN + lcol) = h2;
                } else {
                    __half2 h2 = __floats2half2_rn(v0, v1);
                    *(__half2*)(g_Yh + crow * DD + nt * BN + lcol) = h2;
                }
            }
        }
    }
}

// ============================ routing ======================================
__global__ void logits_kernel(const float* __restrict__ x, const float* __restrict__ Wr) {
    const int t = blockIdx.x;
    const int tid = threadIdx.x;           // 256
    const float* xr = x + (size_t)t * DD;
    float p[8] = {0, 0, 0, 0, 0, 0, 0, 0};
    for (int d = tid; d < DD; d += 256) {
        float xv = xr[d];
        const float4 w0 = *(const float4*)(Wr + d * 8);
        const float4 w1 = *(const float4*)(Wr + d * 8 + 4);
        p[0] += xv * w0.x; p[1] += xv * w0.y; p[2] += xv * w0.z; p[3] += xv * w0.w;
        p[4] += xv * w1.x; p[5] += xv * w1.y; p[6] += xv * w1.z; p[7] += xv * w1.w;
    }
    __shared__ float sm[8][256];
    #pragma unroll
    for (int e = 0; e < 8; ++e) sm[e][tid] = p[e];
    __syncthreads();
    for (int off = 128; off > 0; off >>= 1) {
        if (tid < off) {
            #pragma unroll
            for (int e = 0; e < 8; ++e) sm[e][tid] += sm[e][tid + off];
        }
        __syncthreads();
    }
    if (tid < 8) {
        unsigned k = __float_as_uint(sm[tid][0]);
        k = (k & 0x80000000u) ? ~k : (k | 0x80000000u);
        g_keys[tid * NT + t] = k;
    }
}

// shfl-based exclusive scan over 1024 threads (2 barriers instead of ~20)
__device__ int block_exscan(int v, int* warpsums, int tid) {
    const int lane = tid & 31, w = tid >> 5;      // 32 warps
    int s = v;
    #pragma unroll
    for (int d = 1; d < 32; d <<= 1) {
        int t = __shfl_up_sync(0xFFFFFFFFu, s, d);
        if (lane >= d) s += t;
    }
    if (lane == 31) warpsums[w] = s;
    __syncthreads();
    if (w == 0) {
        int ws = warpsums[lane];
        #pragma unroll
        for (int d = 1; d < 32; d <<= 1) {
            int t = __shfl_up_sync(0xFFFFFFFFu, ws, d);
            if (lane >= d) ws += t;
        }
        warpsums[lane] = ws;
    }
    __syncthreads();
    const int base = (w > 0) ? warpsums[w - 1] : 0;
    return base + s - v;
}

__global__ void select_kernel() {
    const int e = blockIdx.x;
    const int tid = threadIdx.x;           // 1024
    const unsigned* keys = g_keys + e * NT;
    __shared__ unsigned hist[256];
    __shared__ unsigned sh_prefix, sh_R;
    __shared__ int scan[32];

    unsigned prefix = 0, R = CAPN;
    for (int p = 3; p >= 0; --p) {
        if (tid < 256) hist[tid] = 0u;
        __syncthreads();
        for (int t = tid; t < NT; t += 1024) {
            unsigned k = keys[t];
            if (p == 3 || ((k >> (8 * (p + 1))) == prefix))
                atomicAdd(&hist[(k >> (8 * p)) & 255u], 1u);
        }
        __syncthreads();
        if (tid == 0) {
            unsigned acc = 0; int bsel = 0; unsigned Rn = R;
            for (int v = 255; v >= 0; --v) {
                if (acc + hist[v] >= R) { bsel = v; Rn = R - acc; break; }
                acc += hist[v];
            }
            sh_prefix = (prefix << 8) | (unsigned)bsel;
            sh_R = Rn;
        }
        __syncthreads();
        prefix = sh_prefix; R = sh_R;
        __syncthreads();
    }

    const unsigned Kstar = prefix;
    const int TPT = NT / 1024;             // 16, contiguous per thread
    const int base = tid * TPT;
    int gt = 0, tie = 0;
    for (int i = 0; i < TPT; ++i) {
        unsigned k = keys[base + i];
        gt  += (k > Kstar);
        tie += (k == Kstar);
    }
    int tie_off = block_exscan(tie, scan, tid);
    int take = (int)R - tie_off;
    if (take < 0) take = 0;
    if (take > tie) take = tie;
    int slot_off = block_exscan(gt + take, scan, tid);

    int slot = slot_off, trank = tie_off;
    for (int i = 0; i < TPT; ++i) {
        const int t = base + i;
        const unsigned k = keys[t];
        int s = -1;
        if (k > Kstar)       s = slot++;
        else if (k == Kstar) { if (trank < (int)R) s = slot++; trank++; }
        g_inv[e * NT + t] = s;
        if (s >= 0) g_sel[e * CAPN + s] = t;
    }
}

// ============================ fused prep ===================================
// transpose tiles are 64(m) x 32(n): reads AND writes both 128B-coalesced.
#define PREP_W1_BLOCKS (NE * (DD / 64) * (FF / 32))   // 16384
#define PREP_W2_BLOCKS (NE * (FF / 64) * (DD / 32))   // 16384
#define PREP_GATHER_OFF (PREP_W1_BLOCKS + PREP_W2_BLOCKS)
__global__ void prep_kernel(const float* __restrict__ W1,
                            const float* __restrict__ W2,
                            const float* __restrict__ x) {
    const int bid = blockIdx.x;
    const int tid = threadIdx.x;            // 256
    if (bid < PREP_GATHER_OFF) {
        const int which = (bid >= PREP_W1_BLOCKS);
        const int lb = which ? (bid - PREP_W1_BLOCKS) : bid;
        const int M = which ? FF : DD;      // source rows (m)
        const int N = which ? DD : FF;      // source cols (n)
        const int ntile = N / 32;
        const int per_e = (M / 64) * ntile;
        const int e  = lb / per_e;
        const int r  = lb % per_e;
        const int n0 = (r % ntile) * 32;
        const int m0 = (r / ntile) * 64;
        const float* I = (which ? W2 : W1) + (size_t)e * M * N;
        __half* O = (which ? g_W2t : g_W1t) + (size_t)e * M * N;
        __shared__ float tile[64][33];
        {   // read: 64 rows x 32 cols, rows 8 at a time
            const int tx = tid & 31, ty = tid >> 5;         // ty in [0,8)
            #pragma unroll
            for (int k = 0; k < 64; k += 8)
                tile[ty + k][tx] = I[(size_t)(m0 + ty + k) * N + n0 + tx];
        }
        __syncthreads();
        {   // write: 32 out-rows (n) x 64 out-cols (m), n 4 at a time
            const int tx = tid & 63, ty = tid >> 6;         // ty in [0,4)
            #pragma unroll
            for (int k = 0; k < 32; k += 4)
                O[(size_t)(n0 + ty + k) * M + m0 + tx] = __float2half(tile[tx][ty + k]);
        }
    } else {
        const int r = (bid - PREP_GATHER_OFF) * 2 + (tid >> 7);   // e*CAPN + slot
        const int lt = tid & 127;
        const int tok = g_sel[r];
        const float* src = x + (size_t)tok * DD;
        __half* dst = g_Xp + (size_t)r * DD;
        float4 a = ((const float4*)src)[lt * 2];
        float4 b = ((const float4*)src)[lt * 2 + 1];
        __half2 h0 = __floats2half2_rn(a.x, a.y);
        __half2 h1 = __floats2half2_rn(a.z, a.w);
        __half2 h2 = __floats2half2_rn(b.x, b.y);
        __half2 h3 = __floats2half2_rn(b.z, b.w);
        uint4 o;
        o.x = *(uint32_t*)&h0; o.y = *(uint32_t*)&h1;
        o.z = *(uint32_t*)&h2; o.w = *(uint32_t*)&h3;
        ((uint4*)dst)[lt] = o;
    }
}

__global__ void combine_kernel(float* __restrict__ out) {
    const int t = blockIdx.x;
    const int tid = threadIdx.x;            // 256, 4 floats each
    __shared__ int inv[8];
    if (tid < 8) inv[tid] = g_inv[tid * NT + t];
    __syncthreads();
    float4 acc = make_float4(0.f, 0.f, 0.f, 0.f);
    #pragma unroll
    for (int e = 0; e < 8; ++e) {
        const int s = inv[e];
        if (s >= 0) {
            const uint2 raw = *(const uint2*)(g_Yh + ((size_t)(e * CAPN + s)) * DD + tid * 4);
            const __half2 y0 = *(const __half2*)&raw.x;
            const __half2 y1 = *(const __half2*)&raw.y;
            float2 f0 = __half22float2(y0);
            float2 f1 = __half22float2(y1);
            acc.x += f0.x; acc.y += f0.y; acc.z += f1.x; acc.w += f1.y;
        }
    }
    *(float4*)(out + (size_t)t * DD + tid * 4) = acc;
}

// ============================ launch =======================================
extern "C" void kernel_launch(void* const* d_in, const int* in_sizes, int n_in,
                              void* d_out, int out_size) {
    (void)in_sizes; (void)n_in; (void)out_size;
    const float* x  = (const float*)d_in[0];
    const float* Wr = (const float*)d_in[1];
    const float* W1 = (const float*)d_in[2];
    const float* b1 = (const float*)d_in[3];
    const float* W2 = (const float*)d_in[4];
    const float* b2 = (const float*)d_in[5];
    float* out = (float*)d_out;

    cudaFuncSetAttribute(gemm_kernel<true>,  cudaFuncAttributeMaxDynamicSharedMemorySize, SMEM_TOTAL);
    cudaFuncSetAttribute(gemm_kernel<false>, cudaFuncAttributeMaxDynamicSharedMemorySize, SMEM_TOTAL);

    // launch order keeps gemm_kernel<true> in the ncu capture slot.
    logits_kernel<<<NT, 256>>>(x, Wr);
    select_kernel<<<NE, 1024>>>();
    prep_kernel<<<PREP_GATHER_OFF + NE * CAPN / 2, 256>>>(W1, W2, x);

    gemm_kernel<true ><<<dim3(FF / BN, CAPN / BM, NE), GTHREADS, SMEM_TOTAL>>>(b1);
    gemm_kernel<false><<<dim3(DD / BN, CAPN / BM, NE), GTHREADS, SMEM_TOTAL>>>(b2);

    combine_kernel<<<NT, 256>>>(out);
}